// round 3
// baseline (speedup 1.0000x reference)
#include <cuda_runtime.h>
#include <math.h>

#define N_NODES 8192
#define N_EDGES 32768
#define HID     8
#define FEAT    11          // HID + 3
#define CHUNK   16

// Scratch: recovered gather indices (each edge written exactly once per scan)
__device__ int g_idx_i[N_EDGES];
__device__ int g_idx_o[N_EDGES];

// ---------------------------------------------------------------------------
// Kernel 1: recover one-hot indices with per-column EARLY EXIT.
// R is [N_NODES, N_EDGES] row-major; column e has exactly one 1.0.
// Each thread owns one full column and stops loading once its hit is found.
// Predicated-off lanes stop contributing 32B sectors -> expected DRAM traffic
// = E[max of 8 uniform hit positions] = 8/9 of the full matrix.
// ---------------------------------------------------------------------------
__global__ void __launch_bounds__(128)
scan_onehot_kernel(const float* __restrict__ Ri, const float* __restrict__ Ro)
{
    const int col = blockIdx.x * blockDim.x + threadIdx.x;   // 0..N_EDGES-1
    const float* __restrict__ R = blockIdx.z ? Ro : Ri;
    int* __restrict__ idx       = blockIdx.z ? g_idx_o : g_idx_i;

    const float* __restrict__ p = R + col;
    float f = 0.f;

    for (int k = 0; k < N_NODES; k += CHUNK) {
        float v[CHUNK];
#pragma unroll
        for (int i = 0; i < CHUNK; ++i)
            v[i] = __ldcs(p + (size_t)(k + i) * N_EDGES);   // streaming, read-once
#pragma unroll
        for (int i = 0; i < CHUNK; ++i)
            f = fmaf(v[i], (float)(k + i + 1), f);          // hit at n -> f = n+1 (exact)
        if (f != 0.f) break;                                // this lane is done
    }

    idx[col] = (int)f - 1;
}

// ---------------------------------------------------------------------------
// Kernel 2: fused gather + 2-layer MLP per edge.
// B[e] = [X[idx_o[e]], X[idx_i[e]]] (22) -> tanh(.@W1+b1) (8) -> sigmoid(.@W2+b2)
// ---------------------------------------------------------------------------
__global__ void __launch_bounds__(128)
edge_mlp_kernel(const float* __restrict__ X,
                const float* __restrict__ W1, const float* __restrict__ b1,
                const float* __restrict__ W2, const float* __restrict__ b2,
                float* __restrict__ out)
{
    __shared__ float sW1[2 * FEAT * HID];  // [22][8] = 176 floats
    __shared__ float sb1[HID];
    __shared__ float sW2[HID];
    __shared__ float sb2;

    const int t = threadIdx.x;
    // strided load: block size may be smaller than 176
    for (int i = t; i < 2 * FEAT * HID; i += blockDim.x) sW1[i] = W1[i];
    if (t < HID)  { sb1[t] = b1[t]; sW2[t] = W2[t]; }
    if (t == 0)   sb2 = b2[0];
    __syncthreads();

    const int e = blockIdx.x * blockDim.x + t;
    if (e >= N_EDGES) return;

    const float* __restrict__ xo = X + (size_t)g_idx_o[e] * FEAT;
    const float* __restrict__ xi = X + (size_t)g_idx_i[e] * FEAT;

    float h[HID];
#pragma unroll
    for (int j = 0; j < HID; ++j) h[j] = sb1[j];

#pragma unroll
    for (int f = 0; f < FEAT; ++f) {
        const float v = __ldg(xo + f);
#pragma unroll
        for (int j = 0; j < HID; ++j) h[j] = fmaf(v, sW1[f * HID + j], h[j]);
    }
#pragma unroll
    for (int f = 0; f < FEAT; ++f) {
        const float v = __ldg(xi + f);
#pragma unroll
        for (int j = 0; j < HID; ++j) h[j] = fmaf(v, sW1[(FEAT + f) * HID + j], h[j]);
    }

    float s = sb2;
#pragma unroll
    for (int j = 0; j < HID; ++j) s = fmaf(tanhf(h[j]), sW2[j], s);

    out[e] = 1.0f / (1.0f + expf(-s));
}

// ---------------------------------------------------------------------------
// Inputs (metadata order): X, Ri, Ro, W1, b1, W2, b2. Output: float [N_EDGES].
// ---------------------------------------------------------------------------
extern "C" void kernel_launch(void* const* d_in, const int* in_sizes, int n_in,
                              void* d_out, int out_size)
{
    const float* X  = (const float*)d_in[0];
    const float* Ri = (const float*)d_in[1];
    const float* Ro = (const float*)d_in[2];
    const float* W1 = (const float*)d_in[3];
    const float* b1 = (const float*)d_in[4];
    const float* W2 = (const float*)d_in[5];
    const float* b2 = (const float*)d_in[6];
    float* out = (float*)d_out;

    // Scan: one thread per column, full-column ownership for early exit.
    dim3 sgrid(N_EDGES / 128, 1, 2);
    scan_onehot_kernel<<<sgrid, 128>>>(Ri, Ro);

    // MLP: 256 CTAs x 128 threads = 32768 edges
    edge_mlp_kernel<<<N_EDGES / 128, 128>>>(X, W1, b1, W2, b2, out);
}

// round 4
// speedup vs baseline: 1.0246x; 1.0246x over previous
#include <cuda_runtime.h>
#include <math.h>

#define N_NODES 8192
#define N_EDGES 32768
#define HID     8
#define FEAT    11          // HID + 3
#define CHUNK   16

// Scratch: recovered gather indices (each edge written exactly once per scan)
__device__ int g_idx_i[N_EDGES];
__device__ int g_idx_o[N_EDGES];

// ---------------------------------------------------------------------------
// Kernel 1: recover one-hot indices with per-column EARLY EXIT, double-buffered.
// R is [N_NODES, N_EDGES] row-major; column e has exactly one 1.0.
// Each thread owns one full column. The next chunk's loads are issued BEFORE
// the current chunk is accumulated / exit-checked, so DRAM latency is always
// covered by in-flight loads (the R3 version stalled at every chunk boundary).
// Retired lanes stop contributing 32B sectors -> expected DRAM traffic
// = E[max of 8 uniform hit positions] = 8/9 of the full matrix.
// ---------------------------------------------------------------------------
__global__ void __launch_bounds__(64)
scan_onehot_kernel(const float* __restrict__ Ri, const float* __restrict__ Ro)
{
    const int col = blockIdx.x * blockDim.x + threadIdx.x;   // 0..N_EDGES-1
    const float* __restrict__ R = blockIdx.z ? Ro : Ri;
    int* __restrict__ idx       = blockIdx.z ? g_idx_o : g_idx_i;

    const float* __restrict__ p = R + col;
    float f = 0.f;

    float v[CHUNK];
#pragma unroll
    for (int i = 0; i < CHUNK; ++i)                          // prologue: chunk 0
        v[i] = __ldcs(p + (size_t)i * N_EDGES);

#pragma unroll 2
    for (int k = 0; k < N_NODES; k += CHUNK) {
        float w[CHUNK];
        const int kn = k + CHUNK;
        if (kn < N_NODES) {
#pragma unroll
            for (int i = 0; i < CHUNK; ++i)                  // prefetch next chunk
                w[i] = __ldcs(p + (size_t)(kn + i) * N_EDGES);
        }
#pragma unroll
        for (int i = 0; i < CHUNK; ++i)
            f = fmaf(v[i], (float)(k + i + 1), f);           // hit at n -> f = n+1
        if (f != 0.f) break;                                 // lane done
#pragma unroll
        for (int i = 0; i < CHUNK; ++i) v[i] = w[i];
    }

    idx[col] = (int)f - 1;
}

// ---------------------------------------------------------------------------
// Kernel 2: fused gather + 2-layer MLP per edge.
// B[e] = [X[idx_o[e]], X[idx_i[e]]] (22) -> tanh(.@W1+b1) (8) -> sigmoid(.@W2+b2)
// ---------------------------------------------------------------------------
__global__ void __launch_bounds__(128)
edge_mlp_kernel(const float* __restrict__ X,
                const float* __restrict__ W1, const float* __restrict__ b1,
                const float* __restrict__ W2, const float* __restrict__ b2,
                float* __restrict__ out)
{
    __shared__ float sW1[2 * FEAT * HID];  // [22][8] = 176 floats
    __shared__ float sb1[HID];
    __shared__ float sW2[HID];
    __shared__ float sb2;

    const int t = threadIdx.x;
    for (int i = t; i < 2 * FEAT * HID; i += blockDim.x) sW1[i] = W1[i];
    if (t < HID)  { sb1[t] = b1[t]; sW2[t] = W2[t]; }
    if (t == 0)   sb2 = b2[0];
    __syncthreads();

    const int e = blockIdx.x * blockDim.x + t;
    if (e >= N_EDGES) return;

    const float* __restrict__ xo = X + (size_t)g_idx_o[e] * FEAT;
    const float* __restrict__ xi = X + (size_t)g_idx_i[e] * FEAT;

    float h[HID];
#pragma unroll
    for (int j = 0; j < HID; ++j) h[j] = sb1[j];

#pragma unroll
    for (int f = 0; f < FEAT; ++f) {
        const float v = __ldg(xo + f);
#pragma unroll
        for (int j = 0; j < HID; ++j) h[j] = fmaf(v, sW1[f * HID + j], h[j]);
    }
#pragma unroll
    for (int f = 0; f < FEAT; ++f) {
        const float v = __ldg(xi + f);
#pragma unroll
        for (int j = 0; j < HID; ++j) h[j] = fmaf(v, sW1[(FEAT + f) * HID + j], h[j]);
    }

    float s = sb2;
#pragma unroll
    for (int j = 0; j < HID; ++j) s = fmaf(tanhf(h[j]), sW2[j], s);

    out[e] = 1.0f / (1.0f + expf(-s));
}

// ---------------------------------------------------------------------------
// Inputs (metadata order): X, Ri, Ro, W1, b1, W2, b2. Output: float [N_EDGES].
// ---------------------------------------------------------------------------
extern "C" void kernel_launch(void* const* d_in, const int* in_sizes, int n_in,
                              void* d_out, int out_size)
{
    const float* X  = (const float*)d_in[0];
    const float* Ri = (const float*)d_in[1];
    const float* Ro = (const float*)d_in[2];
    const float* W1 = (const float*)d_in[3];
    const float* b1 = (const float*)d_in[4];
    const float* W2 = (const float*)d_in[5];
    const float* b2 = (const float*)d_in[6];
    float* out = (float*)d_out;

    // Scan: one thread per column; 64-thread CTAs for smooth wave balance.
    dim3 sgrid(N_EDGES / 64, 1, 2);
    scan_onehot_kernel<<<sgrid, 64>>>(Ri, Ro);

    // MLP: 256 CTAs x 128 threads = 32768 edges
    edge_mlp_kernel<<<N_EDGES / 128, 128>>>(X, W1, b1, W2, b2, out);
}

// round 5
// speedup vs baseline: 1.3513x; 1.3188x over previous
#include <cuda_runtime.h>
#include <math.h>

#define N_NODES 8192
#define N_EDGES 32768
#define HID     8
#define FEAT    11              // HID + 3
#define EG2     (N_EDGES / 8)   // 4096 8-float groups per row
#define SLAB    128
#define NSLABS  (N_NODES / SLAB) // 64

// Scratch: recovered gather indices (each edge written exactly once per scan)
__device__ int g_idx_i[N_EDGES];
__device__ int g_idx_o[N_EDGES];

// ---------------------------------------------------------------------------
// Kernel 1: recover one-hot indices from dense incidence matrices.
// R is [N_NODES, N_EDGES] row-major. Column e has exactly one 1.0.
// idx[e] = sum_n R[n,e] * (n+1) - 1   (branch-free FFMA accumulation)
// Each thread owns 8 adjacent columns (32B per row); a warp streams 1024B
// contiguous per row. No data-dependent branches -> ptxas front-batches loads.
// ---------------------------------------------------------------------------
__global__ void __launch_bounds__(256)
scan_onehot_kernel(const float* __restrict__ Ri, const float* __restrict__ Ro)
{
    const int g    = blockIdx.x * blockDim.x + threadIdx.x;  // 8-edge group
    const int slab = blockIdx.y;
    const float* __restrict__ R = (blockIdx.z == 0) ? Ri : Ro;
    int* __restrict__ idx       = (blockIdx.z == 0) ? g_idx_i : g_idx_o;

    const float4* __restrict__ p =
        reinterpret_cast<const float4*>(R) + (size_t)slab * SLAB * (EG2 * 2) + 2 * g;

    float fa[8];
#pragma unroll
    for (int i = 0; i < 8; ++i) fa[i] = 0.f;

    const int n0 = slab * SLAB;

#pragma unroll 4
    for (int k = 0; k < SLAB; ++k) {
        float4 a = __ldcs(p);           // edges [8g .. 8g+3]
        float4 b = __ldcs(p + 1);       // edges [8g+4 .. 8g+7]
        p += EG2 * 2;
        const float w = (float)(n0 + k + 1); // +1 so hit at n=0 is distinguishable
        fa[0] = fmaf(a.x, w, fa[0]);
        fa[1] = fmaf(a.y, w, fa[1]);
        fa[2] = fmaf(a.z, w, fa[2]);
        fa[3] = fmaf(a.w, w, fa[3]);
        fa[4] = fmaf(b.x, w, fa[4]);
        fa[5] = fmaf(b.y, w, fa[5]);
        fa[6] = fmaf(b.z, w, fa[6]);
        fa[7] = fmaf(b.w, w, fa[7]);
    }

    const int e = 8 * g;
#pragma unroll
    for (int i = 0; i < 8; ++i)
        if (fa[i] != 0.f) idx[e + i] = (int)fa[i] - 1;
}

// ---------------------------------------------------------------------------
// Kernel 2: fused gather + 2-layer MLP per edge.
// B[e] = [X[idx_o[e]], X[idx_i[e]]] (22) -> tanh(.@W1+b1) (8) -> sigmoid(.@W2+b2)
// ---------------------------------------------------------------------------
__global__ void __launch_bounds__(256)
edge_mlp_kernel(const float* __restrict__ X,
                const float* __restrict__ W1, const float* __restrict__ b1,
                const float* __restrict__ W2, const float* __restrict__ b2,
                float* __restrict__ out)
{
    __shared__ float sW1[2 * FEAT * HID];  // [22][8] = 176 floats
    __shared__ float sb1[HID];
    __shared__ float sW2[HID];
    __shared__ float sb2;

    const int t = threadIdx.x;
    for (int i = t; i < 2 * FEAT * HID; i += blockDim.x) sW1[i] = W1[i];
    if (t < HID)  { sb1[t] = b1[t]; sW2[t] = W2[t]; }
    if (t == 0)   sb2 = b2[0];
    __syncthreads();

    const int e = blockIdx.x * blockDim.x + t;
    if (e >= N_EDGES) return;

    const float* __restrict__ xo = X + (size_t)g_idx_o[e] * FEAT;
    const float* __restrict__ xi = X + (size_t)g_idx_i[e] * FEAT;

    float h[HID];
#pragma unroll
    for (int j = 0; j < HID; ++j) h[j] = sb1[j];

#pragma unroll
    for (int f = 0; f < FEAT; ++f) {
        const float v = __ldg(xo + f);
#pragma unroll
        for (int j = 0; j < HID; ++j) h[j] = fmaf(v, sW1[f * HID + j], h[j]);
    }
#pragma unroll
    for (int f = 0; f < FEAT; ++f) {
        const float v = __ldg(xi + f);
#pragma unroll
        for (int j = 0; j < HID; ++j) h[j] = fmaf(v, sW1[(FEAT + f) * HID + j], h[j]);
    }

    float s = sb2;
#pragma unroll
    for (int j = 0; j < HID; ++j) s = fmaf(tanhf(h[j]), sW2[j], s);

    out[e] = 1.0f / (1.0f + expf(-s));
}

// ---------------------------------------------------------------------------
// Inputs (metadata order): X, Ri, Ro, W1, b1, W2, b2. Output: float [N_EDGES].
// ---------------------------------------------------------------------------
extern "C" void kernel_launch(void* const* d_in, const int* in_sizes, int n_in,
                              void* d_out, int out_size)
{
    const float* X  = (const float*)d_in[0];
    const float* Ri = (const float*)d_in[1];
    const float* Ro = (const float*)d_in[2];
    const float* W1 = (const float*)d_in[3];
    const float* b1 = (const float*)d_in[4];
    const float* W2 = (const float*)d_in[5];
    const float* b2 = (const float*)d_in[6];
    float* out = (float*)d_out;

    // Scan: 16 edge-blocks x 64 n-slabs x 2 matrices = 2048 CTAs
    dim3 sgrid(EG2 / 256, NSLABS, 2);
    scan_onehot_kernel<<<sgrid, 256>>>(Ri, Ro);

    // MLP: 128 CTAs x 256 threads = 32768 edges
    edge_mlp_kernel<<<N_EDGES / 256, 256>>>(X, W1, b1, W2, b2, out);
}

// round 6
// speedup vs baseline: 1.4223x; 1.0526x over previous
#include <cuda_runtime.h>
#include <math.h>

#define N_NODES 8192
#define N_EDGES 32768
#define HID     8
#define FEAT    11          // HID + 3
#define EG      (N_EDGES / 4)   // 8192 float4 groups per row
#define SLAB    128
#define NSLABS  (N_NODES / SLAB) // 64

// Scratch: recovered gather indices (each edge written exactly once per scan)
__device__ int g_idx_i[N_EDGES];
__device__ int g_idx_o[N_EDGES];

// ---------------------------------------------------------------------------
// Kernel 1: recover one-hot indices from dense incidence matrices.
// R is [N_NODES, N_EDGES] row-major. Column e has exactly one 1.0.
// idx[e] = sum_n R[n,e] * (n+1)  - 1   (branch-free FFMA accumulation)
// Proven-best config (R1, 294us): 1M threads, float4/thread, unroll 8,
// no data-dependent branches -> ptxas front-batches 8 LDG.128 per thread.
// ---------------------------------------------------------------------------
__global__ void __launch_bounds__(256)
scan_onehot_kernel(const float* __restrict__ Ri, const float* __restrict__ Ro)
{
    const int g    = blockIdx.x * blockDim.x + threadIdx.x;  // float4 group (4 edges)
    const int slab = blockIdx.y;
    const float* __restrict__ R = (blockIdx.z == 0) ? Ri : Ro;
    int* __restrict__ idx       = (blockIdx.z == 0) ? g_idx_i : g_idx_o;

    const float4* __restrict__ p =
        reinterpret_cast<const float4*>(R) + (size_t)slab * SLAB * EG + g;

    float fx = 0.f, fy = 0.f, fz = 0.f, fw = 0.f;
    const int n0 = slab * SLAB;

#pragma unroll 8
    for (int k = 0; k < SLAB; ++k) {
        float4 v = __ldcs(p);          // streaming load, read-once data
        p += EG;
        float w = (float)(n0 + k + 1); // +1 so a hit at n=0 is distinguishable
        fx = fmaf(v.x, w, fx);
        fy = fmaf(v.y, w, fy);
        fz = fmaf(v.z, w, fz);
        fw = fmaf(v.w, w, fw);
    }

    const int e = 4 * g;
    if (fx != 0.f) idx[e + 0] = (int)fx - 1;
    if (fy != 0.f) idx[e + 1] = (int)fy - 1;
    if (fz != 0.f) idx[e + 2] = (int)fz - 1;
    if (fw != 0.f) idx[e + 3] = (int)fw - 1;
}

// ---------------------------------------------------------------------------
// Kernel 2: fused gather + 2-layer MLP per edge.
// B[e] = [X[idx_o[e]], X[idx_i[e]]] (22) -> tanh(.@W1+b1) (8) -> sigmoid(.@W2+b2)
// ---------------------------------------------------------------------------
__global__ void __launch_bounds__(256)
edge_mlp_kernel(const float* __restrict__ X,
                const float* __restrict__ W1, const float* __restrict__ b1,
                const float* __restrict__ W2, const float* __restrict__ b2,
                float* __restrict__ out)
{
    __shared__ float sW1[2 * FEAT * HID];  // [22][8] = 176 floats
    __shared__ float sb1[HID];
    __shared__ float sW2[HID];
    __shared__ float sb2;

    const int t = threadIdx.x;
    for (int i = t; i < 2 * FEAT * HID; i += blockDim.x) sW1[i] = W1[i];
    if (t < HID)  { sb1[t] = b1[t]; sW2[t] = W2[t]; }
    if (t == 0)   sb2 = b2[0];
    __syncthreads();

    const int e = blockIdx.x * blockDim.x + t;
    if (e >= N_EDGES) return;

    const float* __restrict__ xo = X + (size_t)g_idx_o[e] * FEAT;
    const float* __restrict__ xi = X + (size_t)g_idx_i[e] * FEAT;

    float h[HID];
#pragma unroll
    for (int j = 0; j < HID; ++j) h[j] = sb1[j];

#pragma unroll
    for (int f = 0; f < FEAT; ++f) {
        const float v = __ldg(xo + f);
#pragma unroll
        for (int j = 0; j < HID; ++j) h[j] = fmaf(v, sW1[f * HID + j], h[j]);
    }
#pragma unroll
    for (int f = 0; f < FEAT; ++f) {
        const float v = __ldg(xi + f);
#pragma unroll
        for (int j = 0; j < HID; ++j) h[j] = fmaf(v, sW1[(FEAT + f) * HID + j], h[j]);
    }

    float s = sb2;
#pragma unroll
    for (int j = 0; j < HID; ++j) s = fmaf(tanhf(h[j]), sW2[j], s);

    out[e] = 1.0f / (1.0f + expf(-s));
}

// ---------------------------------------------------------------------------
// Inputs (metadata order): X, Ri, Ro, W1, b1, W2, b2. Output: float [N_EDGES].
// ---------------------------------------------------------------------------
extern "C" void kernel_launch(void* const* d_in, const int* in_sizes, int n_in,
                              void* d_out, int out_size)
{
    const float* X  = (const float*)d_in[0];
    const float* Ri = (const float*)d_in[1];
    const float* Ro = (const float*)d_in[2];
    const float* W1 = (const float*)d_in[3];
    const float* b1 = (const float*)d_in[4];
    const float* W2 = (const float*)d_in[5];
    const float* b2 = (const float*)d_in[6];
    float* out = (float*)d_out;

    // Scan: 32 edge-blocks x 64 n-slabs x 2 matrices = 4096 CTAs
    dim3 sgrid(EG / 256, NSLABS, 2);
    scan_onehot_kernel<<<sgrid, 256>>>(Ri, Ro);

    // MLP: 128 CTAs x 256 threads = 32768 edges
    edge_mlp_kernel<<<N_EDGES / 256, 256>>>(X, W1, b1, W2, b2, out);
}

// round 7
// speedup vs baseline: 1.4340x; 1.0082x over previous
#include <cuda_runtime.h>
#include <math.h>

#define N_NODES 8192
#define N_EDGES 32768
#define HID     8
#define FEAT    11          // HID + 3
#define EG      (N_EDGES / 4)   // 8192 float4 groups per row
#define SLAB    64
#define NSLABS  (N_NODES / SLAB) // 128

// Scratch: recovered gather indices (each edge written exactly once per scan)
__device__ int g_idx_i[N_EDGES];
__device__ int g_idx_o[N_EDGES];

// ---------------------------------------------------------------------------
// Kernel 1: recover one-hot indices from dense incidence matrices.
// R is [N_NODES, N_EDGES] row-major. Column e has exactly one 1.0.
// idx[e] = sum_n R[n,e] * (n+1)  - 1   (branch-free FFMA accumulation)
// Proven-best access pattern (R1): float4/thread, unroll 8, no data-dependent
// branches. This round: SLAB 128->64 (8192 CTAs) to halve the wave-
// quantization tail (~55 sequential CTAs/SM -> ~1.8% finish spread).
// ---------------------------------------------------------------------------
__global__ void __launch_bounds__(256)
scan_onehot_kernel(const float* __restrict__ Ri, const float* __restrict__ Ro)
{
    const int g    = blockIdx.x * blockDim.x + threadIdx.x;  // float4 group (4 edges)
    const int slab = blockIdx.y;
    const float* __restrict__ R = (blockIdx.z == 0) ? Ri : Ro;
    int* __restrict__ idx       = (blockIdx.z == 0) ? g_idx_i : g_idx_o;

    const float4* __restrict__ p =
        reinterpret_cast<const float4*>(R) + (size_t)slab * SLAB * EG + g;

    float fx = 0.f, fy = 0.f, fz = 0.f, fw = 0.f;
    const int n0 = slab * SLAB;

#pragma unroll 8
    for (int k = 0; k < SLAB; ++k) {
        float4 v = __ldcs(p);          // streaming load, read-once data
        p += EG;
        float w = (float)(n0 + k + 1); // +1 so a hit at n=0 is distinguishable
        fx = fmaf(v.x, w, fx);
        fy = fmaf(v.y, w, fy);
        fz = fmaf(v.z, w, fz);
        fw = fmaf(v.w, w, fw);
    }

    const int e = 4 * g;
    if (fx != 0.f) idx[e + 0] = (int)fx - 1;
    if (fy != 0.f) idx[e + 1] = (int)fy - 1;
    if (fz != 0.f) idx[e + 2] = (int)fz - 1;
    if (fw != 0.f) idx[e + 3] = (int)fw - 1;
}

// ---------------------------------------------------------------------------
// Kernel 2: fused gather + 2-layer MLP per edge.
// B[e] = [X[idx_o[e]], X[idx_i[e]]] (22) -> tanh(.@W1+b1) (8) -> sigmoid(.@W2+b2)
// ---------------------------------------------------------------------------
__global__ void __launch_bounds__(256)
edge_mlp_kernel(const float* __restrict__ X,
                const float* __restrict__ W1, const float* __restrict__ b1,
                const float* __restrict__ W2, const float* __restrict__ b2,
                float* __restrict__ out)
{
    __shared__ float sW1[2 * FEAT * HID];  // [22][8] = 176 floats
    __shared__ float sb1[HID];
    __shared__ float sW2[HID];
    __shared__ float sb2;

    const int t = threadIdx.x;
    for (int i = t; i < 2 * FEAT * HID; i += blockDim.x) sW1[i] = W1[i];
    if (t < HID)  { sb1[t] = b1[t]; sW2[t] = W2[t]; }
    if (t == 0)   sb2 = b2[0];
    __syncthreads();

    const int e = blockIdx.x * blockDim.x + t;
    if (e >= N_EDGES) return;

    const float* __restrict__ xo = X + (size_t)g_idx_o[e] * FEAT;
    const float* __restrict__ xi = X + (size_t)g_idx_i[e] * FEAT;

    float h[HID];
#pragma unroll
    for (int j = 0; j < HID; ++j) h[j] = sb1[j];

#pragma unroll
    for (int f = 0; f < FEAT; ++f) {
        const float v = __ldg(xo + f);
#pragma unroll
        for (int j = 0; j < HID; ++j) h[j] = fmaf(v, sW1[f * HID + j], h[j]);
    }
#pragma unroll
    for (int f = 0; f < FEAT; ++f) {
        const float v = __ldg(xi + f);
#pragma unroll
        for (int j = 0; j < HID; ++j) h[j] = fmaf(v, sW1[(FEAT + f) * HID + j], h[j]);
    }

    float s = sb2;
#pragma unroll
    for (int j = 0; j < HID; ++j) s = fmaf(tanhf(h[j]), sW2[j], s);

    out[e] = 1.0f / (1.0f + expf(-s));
}

// ---------------------------------------------------------------------------
// Inputs (metadata order): X, Ri, Ro, W1, b1, W2, b2. Output: float [N_EDGES].
// ---------------------------------------------------------------------------
extern "C" void kernel_launch(void* const* d_in, const int* in_sizes, int n_in,
                              void* d_out, int out_size)
{
    const float* X  = (const float*)d_in[0];
    const float* Ri = (const float*)d_in[1];
    const float* Ro = (const float*)d_in[2];
    const float* W1 = (const float*)d_in[3];
    const float* b1 = (const float*)d_in[4];
    const float* W2 = (const float*)d_in[5];
    const float* b2 = (const float*)d_in[6];
    float* out = (float*)d_out;

    // Scan: 32 edge-blocks x 128 n-slabs x 2 matrices = 8192 CTAs
    dim3 sgrid(EG / 256, NSLABS, 2);
    scan_onehot_kernel<<<sgrid, 256>>>(Ri, Ro);

    // MLP: 128 CTAs x 256 threads = 32768 edges
    edge_mlp_kernel<<<N_EDGES / 256, 256>>>(X, W1, b1, W2, b2, out);
}